// round 3
// baseline (speedup 1.0000x reference)
#include <cuda_runtime.h>
#include <math.h>

#define BATCH 64
#define HW 224
#define IMG_PIX (HW * HW)   // 50176

// Scratch: channel-planar copy of the input + the 5x5x3 metric grid per image.
__device__ float g_planar[3ULL * BATCH * IMG_PIX];   // [ch][b][r][c]
__device__ float g_grid[BATCH * 5 * 5 * 3];          // [b][metric][kidx][ch]

// ---------------------------------------------------------------------------
// Pass 1: NHWC -> planar CHW-ish (per-channel contiguous images)
// ---------------------------------------------------------------------------
__global__ void transpose_kernel(const float* __restrict__ in) {
    int idx = blockIdx.x * blockDim.x + threadIdx.x;
    const int total = BATCH * IMG_PIX;
    if (idx < total) {
        const float* p = in + (size_t)idx * 3;
        float v0 = p[0], v1 = p[1], v2 = p[2];
        g_planar[0ULL * total + idx] = v0;
        g_planar[1ULL * total + idx] = v1;
        g_planar[2ULL * total + idx] = v2;
    }
}

// ---------------------------------------------------------------------------
// Pass 2: per-(b, ch, k) block computes all patches and the 5 metrics
// ---------------------------------------------------------------------------
template <int K>
__device__ __forceinline__ void compute_block(int b, int ch, int kidx) {
    constexpr int ROWS = (HW + K - 1) / K;
    constexpr int P = ROWS * ROWS;
    constexpr int PAD = (ROWS * K - HW) / 2;   // == ph // 2 (symmetric, square)
    constexpr int KK = K * K;

    __shared__ int s_hist[KK + 1];
    __shared__ int s_ncomp, s_perc, s_marea;

    for (int i = threadIdx.x; i < KK + 1; i += blockDim.x) s_hist[i] = 0;
    if (threadIdx.x == 0) { s_ncomp = 0; s_perc = 0; s_marea = 0; }
    __syncthreads();

    const float* img = g_planar + ((size_t)ch * BATCH + b) * IMG_PIX;
    const float thr = (float)K;

    int t_ncomp = 0, t_perc = 0, t_marea = 0;

    for (int p = threadIdx.x; p < P; p += blockDim.x) {
        int pr = p / ROWS, pc = p - pr * ROWS;
        int r0 = pr * K - PAD, c0 = pc * K - PAD;

        // center pixel is always in-bounds for these (K, 224) combos
        float cv = __ldg(&img[(r0 + K / 2) * HW + (c0 + K / 2)]);

        unsigned rows[K];
        int ones = 0;
        #pragma unroll
        for (int rr = 0; rr < K; rr++) {
            int r = r0 + rr;
            unsigned m = 0;
            if (r >= 0 && r < HW) {
                const float* rp = img + r * HW;
                #pragma unroll
                for (int cc = 0; cc < K; cc++) {
                    int c = c0 + cc;
                    float v = (c >= 0 && c < HW) ? __ldg(&rp[c]) : 0.0f;
                    if (fabsf(v - cv) <= thr) m |= (1u << cc);
                }
            } else {
                // fully padded row: all values 0
                m = (cv <= thr) ? ((1u << K) - 1u) : 0u;
            }
            rows[rr] = m;
            ones += __popc(m);
        }

        // ---- 4-connected components via bitmask flood fill ----
        unsigned rem[K];
        #pragma unroll
        for (int i = 0; i < K; i++) rem[i] = rows[i];

        int remaining = ones;
        int ncomp = 0, maxc = 0;
        while (remaining > 0) {
            unsigned comp[K];
            #pragma unroll
            for (int i = 0; i < K; i++) comp[i] = 0;
            int seeded = 0;
            #pragma unroll
            for (int i = 0; i < K; i++) {
                if (!seeded && rem[i]) { comp[i] = rem[i] & (0u - rem[i]); seeded = 1; }
            }
            int changed = 1;
            while (changed) {
                changed = 0;
                #pragma unroll
                for (int i = 0; i < K; i++) {          // downward sweep
                    unsigned acc = comp[i] | (comp[i] << 1) | (comp[i] >> 1);
                    if (i > 0) acc |= comp[i - 1];
                    if (i < K - 1) acc |= comp[i + 1];
                    acc &= rem[i];
                    if (acc != comp[i]) { comp[i] = acc; changed = 1; }
                }
                #pragma unroll
                for (int i = K - 1; i >= 0; i--) {     // upward sweep
                    unsigned acc = comp[i] | (comp[i] << 1) | (comp[i] >> 1);
                    if (i > 0) acc |= comp[i - 1];
                    if (i < K - 1) acc |= comp[i + 1];
                    acc &= rem[i];
                    if (acc != comp[i]) { comp[i] = acc; changed = 1; }
                }
            }
            int sz = 0;
            #pragma unroll
            for (int i = 0; i < K; i++) { sz += __popc(comp[i]); rem[i] &= ~comp[i]; }
            remaining -= sz;
            ncomp++;
            if (sz > maxc) maxc = sz;
        }

        int zeros = KK - ones;
        int marea = (zeros > maxc) ? zeros : maxc;   // label-0 (bg) count vs max comp
        int perc = ((float)ones / (float)KK >= 0.59275f) ? 1 : 0;

        atomicAdd(&s_hist[ones], 1);
        t_ncomp += ncomp;
        t_perc += perc;
        t_marea += marea;
    }

    // warp-reduce the three scalar sums, then one shared atomic per warp
    #pragma unroll
    for (int off = 16; off > 0; off >>= 1) {
        t_ncomp += __shfl_down_sync(0xffffffffu, t_ncomp, off);
        t_perc  += __shfl_down_sync(0xffffffffu, t_perc, off);
        t_marea += __shfl_down_sync(0xffffffffu, t_marea, off);
    }
    if ((threadIdx.x & 31) == 0) {
        atomicAdd(&s_ncomp, t_ncomp);
        atomicAdd(&s_perc, t_perc);
        atomicAdd(&s_marea, t_marea);
    }
    __syncthreads();

    if (threadIdx.x == 0) {
        const float Pf = (float)P;
        float fd = 0.f, m = 0.f, m2 = 0.f;
        for (int j = 0; j < KK; j++) {            // bin KK intentionally dropped
            float pr = (float)s_hist[j] / Pf;
            float n = (float)(j + 1);
            fd += pr / n;
            m  += pr * n;
            m2 += pr * pr * n;
        }
        float lac = (m2 - m * m) / (m * m);
        float acn  = (float)(s_ncomp / P);        // tf integer reduce_mean
        float acp  = (float)(s_perc  / P);
        float acma = (float)(s_marea / P);

        float* g = g_grid + (size_t)b * 75;       // [metric][kidx][ch]
        g[(0 * 5 + kidx) * 3 + ch] = acn;
        g[(1 * 5 + kidx) * 3 + ch] = acp;
        g[(2 * 5 + kidx) * 3 + ch] = acma;
        g[(3 * 5 + kidx) * 3 + ch] = lac;
        g[(4 * 5 + kidx) * 3 + ch] = fd;
    }
}

__global__ __launch_bounds__(256) void compute_kernel() {
    int bid = blockIdx.x;
    int kidx = bid / (BATCH * 3);
    int rest = bid - kidx * (BATCH * 3);
    int b = rest / 3, ch = rest - (rest / 3) * 3;
    switch (kidx) {
        case 0: compute_block<3>(b, ch, 0); break;
        case 1: compute_block<5>(b, ch, 1); break;
        case 2: compute_block<7>(b, ch, 2); break;
        case 3: compute_block<9>(b, ch, 3); break;
        case 4: compute_block<11>(b, ch, 4); break;
    }
}

// ---------------------------------------------------------------------------
// Pass 3: bilinear upsample 5x5x3 -> 224x224x3 (half-pixel centers, edge clamp
// == jax.image.resize 'bilinear' for upsampling)
// ---------------------------------------------------------------------------
__global__ void resize_kernel(float* __restrict__ out) {
    int idx = blockIdx.x * blockDim.x + threadIdx.x;   // over BATCH*224*224
    if (idx >= BATCH * IMG_PIX) return;
    int b = idx / IMG_PIX;
    int pix = idx - b * IMG_PIX;
    int i = pix / HW, j = pix - (pix / HW) * HW;

    const float scale = 5.0f / 224.0f;
    float fy = ((float)i + 0.5f) * scale - 0.5f;
    float fx = ((float)j + 0.5f) * scale - 0.5f;
    float y0f = floorf(fy), x0f = floorf(fx);
    float wy = fy - y0f, wx = fx - x0f;
    int y0 = min(4, max(0, (int)y0f));
    int y1 = min(4, max(0, (int)y0f + 1));
    int x0 = min(4, max(0, (int)x0f));
    int x1 = min(4, max(0, (int)x0f + 1));

    const float* g = g_grid + (size_t)b * 75;
    float* o = out + (size_t)idx * 3;
    #pragma unroll
    for (int c = 0; c < 3; c++) {
        float v00 = __ldg(&g[(y0 * 5 + x0) * 3 + c]);
        float v01 = __ldg(&g[(y0 * 5 + x1) * 3 + c]);
        float v10 = __ldg(&g[(y1 * 5 + x0) * 3 + c]);
        float v11 = __ldg(&g[(y1 * 5 + x1) * 3 + c]);
        float top = v00 * (1.0f - wx) + v01 * wx;
        float bot = v10 * (1.0f - wx) + v11 * wx;
        o[c] = top * (1.0f - wy) + bot * wy;
    }
}

// ---------------------------------------------------------------------------
extern "C" void kernel_launch(void* const* d_in, const int* in_sizes, int n_in,
                              void* d_out, int out_size) {
    const float* in = (const float*)d_in[0];
    float* out = (float*)d_out;
    const int npix = BATCH * IMG_PIX;

    transpose_kernel<<<(npix + 255) / 256, 256>>>(in);
    compute_kernel<<<5 * BATCH * 3, 256>>>();
    resize_kernel<<<(npix + 255) / 256, 256>>>(out);
}

// round 4
// speedup vs baseline: 1.0193x; 1.0193x over previous
#include <cuda_runtime.h>
#include <math.h>

#define BATCH 64
#define HW 224
#define IMG_PIX (HW * HW)   // 50176

// Scratch: channel-planar copy of the input + the 5x5x3 metric grid per image.
__device__ float g_planar[3ULL * BATCH * IMG_PIX];   // [ch][b][r][c]
__device__ float g_grid[BATCH * 5 * 5 * 3];          // [b][metric][kidx][ch]

// ---------------------------------------------------------------------------
// Pass 1: NHWC -> planar CHW-ish (per-channel contiguous images)
// ---------------------------------------------------------------------------
__global__ void transpose_kernel(const float* __restrict__ in) {
    int idx = blockIdx.x * blockDim.x + threadIdx.x;
    const int total = BATCH * IMG_PIX;
    if (idx < total) {
        const float* p = in + (size_t)idx * 3;
        float v0 = p[0], v1 = p[1], v2 = p[2];
        g_planar[0ULL * total + idx] = v0;
        g_planar[1ULL * total + idx] = v1;
        g_planar[2ULL * total + idx] = v2;
    }
}

// ---------------------------------------------------------------------------
// Pass 2: per-(b, ch, k) block computes all patches and the 5 metrics
// ---------------------------------------------------------------------------
template <int K>
__device__ __forceinline__ void compute_block(int b, int ch, int kidx) {
    constexpr int ROWS = (HW + K - 1) / K;
    constexpr int P = ROWS * ROWS;
    constexpr int PAD = (ROWS * K - HW) / 2;   // == ph // 2 (symmetric, square)
    constexpr int KK = K * K;

    __shared__ int s_hist[KK + 1];
    __shared__ int s_ncomp, s_perc, s_marea;

    for (int i = threadIdx.x; i < KK + 1; i += blockDim.x) s_hist[i] = 0;
    if (threadIdx.x == 0) { s_ncomp = 0; s_perc = 0; s_marea = 0; }
    __syncthreads();

    const float* img = g_planar + ((size_t)ch * BATCH + b) * IMG_PIX;
    const float thr = (float)K;

    int t_ncomp = 0, t_perc = 0, t_marea = 0;

    for (int p = threadIdx.x; p < P; p += blockDim.x) {
        int pr = p / ROWS, pc = p - pr * ROWS;
        int r0 = pr * K - PAD, c0 = pc * K - PAD;

        // center pixel is always in-bounds for these (K, 224) combos
        float cv = __ldg(&img[(r0 + K / 2) * HW + (c0 + K / 2)]);

        unsigned rows[K];
        int ones = 0;
        #pragma unroll
        for (int rr = 0; rr < K; rr++) {
            int r = r0 + rr;
            unsigned m = 0;
            if (r >= 0 && r < HW) {
                const float* rp = img + r * HW;
                #pragma unroll
                for (int cc = 0; cc < K; cc++) {
                    int c = c0 + cc;
                    float v = (c >= 0 && c < HW) ? __ldg(&rp[c]) : 0.0f;
                    if (fabsf(v - cv) <= thr) m |= (1u << cc);
                }
            } else {
                // fully padded row: all values 0
                m = (cv <= thr) ? ((1u << K) - 1u) : 0u;
            }
            rows[rr] = m;
            ones += __popc(m);
        }

        // ---- 4-connected components via bitmask flood fill ----
        unsigned rem[K];
        #pragma unroll
        for (int i = 0; i < K; i++) rem[i] = rows[i];

        int remaining = ones;
        int ncomp = 0, maxc = 0;
        while (remaining > 0) {
            unsigned comp[K];
            #pragma unroll
            for (int i = 0; i < K; i++) comp[i] = 0;
            int seeded = 0;
            #pragma unroll
            for (int i = 0; i < K; i++) {
                if (!seeded && rem[i]) { comp[i] = rem[i] & (0u - rem[i]); seeded = 1; }
            }
            int changed = 1;
            while (changed) {
                changed = 0;
                #pragma unroll
                for (int i = 0; i < K; i++) {          // downward sweep
                    unsigned acc = comp[i] | (comp[i] << 1) | (comp[i] >> 1);
                    if (i > 0) acc |= comp[i - 1];
                    if (i < K - 1) acc |= comp[i + 1];
                    acc &= rem[i];
                    if (acc != comp[i]) { comp[i] = acc; changed = 1; }
                }
                #pragma unroll
                for (int i = K - 1; i >= 0; i--) {     // upward sweep
                    unsigned acc = comp[i] | (comp[i] << 1) | (comp[i] >> 1);
                    if (i > 0) acc |= comp[i - 1];
                    if (i < K - 1) acc |= comp[i + 1];
                    acc &= rem[i];
                    if (acc != comp[i]) { comp[i] = acc; changed = 1; }
                }
            }
            int sz = 0;
            #pragma unroll
            for (int i = 0; i < K; i++) { sz += __popc(comp[i]); rem[i] &= ~comp[i]; }
            remaining -= sz;
            ncomp++;
            if (sz > maxc) maxc = sz;
        }

        int zeros = KK - ones;
        int marea = (zeros > maxc) ? zeros : maxc;   // label-0 (bg) count vs max comp
        int perc = ((float)ones / (float)KK >= 0.59275f) ? 1 : 0;

        atomicAdd(&s_hist[ones], 1);
        t_ncomp += ncomp;
        t_perc += perc;
        t_marea += marea;
    }

    // warp-reduce the three scalar sums, then one shared atomic per warp
    #pragma unroll
    for (int off = 16; off > 0; off >>= 1) {
        t_ncomp += __shfl_down_sync(0xffffffffu, t_ncomp, off);
        t_perc  += __shfl_down_sync(0xffffffffu, t_perc, off);
        t_marea += __shfl_down_sync(0xffffffffu, t_marea, off);
    }
    if ((threadIdx.x & 31) == 0) {
        atomicAdd(&s_ncomp, t_ncomp);
        atomicAdd(&s_perc, t_perc);
        atomicAdd(&s_marea, t_marea);
    }
    __syncthreads();

    if (threadIdx.x == 0) {
        const float Pf = (float)P;
        float fd = 0.f, m = 0.f, m2 = 0.f;
        for (int j = 0; j < KK; j++) {            // bin KK intentionally dropped
            float pr = (float)s_hist[j] / Pf;
            float n = (float)(j + 1);
            fd += pr / n;
            m  += pr * n;
            m2 += pr * pr * n;
        }
        float lac = (m2 - m * m) / (m * m);
        float acn  = (float)(s_ncomp / P);        // tf integer reduce_mean
        float acp  = (float)(s_perc  / P);
        float acma = (float)(s_marea / P);

        float* g = g_grid + (size_t)b * 75;       // [metric][kidx][ch]
        g[(0 * 5 + kidx) * 3 + ch] = acn;
        g[(1 * 5 + kidx) * 3 + ch] = acp;
        g[(2 * 5 + kidx) * 3 + ch] = acma;
        g[(3 * 5 + kidx) * 3 + ch] = lac;
        g[(4 * 5 + kidx) * 3 + ch] = fd;
    }
}

__global__ __launch_bounds__(256) void compute_kernel() {
    int bid = blockIdx.x;
    int kidx = bid / (BATCH * 3);
    int rest = bid - kidx * (BATCH * 3);
    int b = rest / 3, ch = rest - (rest / 3) * 3;
    switch (kidx) {
        case 0: compute_block<3>(b, ch, 0); break;
        case 1: compute_block<5>(b, ch, 1); break;
        case 2: compute_block<7>(b, ch, 2); break;
        case 3: compute_block<9>(b, ch, 3); break;
        case 4: compute_block<11>(b, ch, 4); break;
    }
}

// ---------------------------------------------------------------------------
// Pass 3: bilinear upsample 5x5x3 -> 224x224x3 (half-pixel centers, edge clamp
// == jax.image.resize 'bilinear' for upsampling)
// ---------------------------------------------------------------------------
__global__ void resize_kernel(float* __restrict__ out) {
    int idx = blockIdx.x * blockDim.x + threadIdx.x;   // over BATCH*224*224
    if (idx >= BATCH * IMG_PIX) return;
    int b = idx / IMG_PIX;
    int pix = idx - b * IMG_PIX;
    int i = pix / HW, j = pix - (pix / HW) * HW;

    const float scale = 5.0f / 224.0f;
    float fy = ((float)i + 0.5f) * scale - 0.5f;
    float fx = ((float)j + 0.5f) * scale - 0.5f;
    float y0f = floorf(fy), x0f = floorf(fx);
    float wy = fy - y0f, wx = fx - x0f;
    int y0 = min(4, max(0, (int)y0f));
    int y1 = min(4, max(0, (int)y0f + 1));
    int x0 = min(4, max(0, (int)x0f));
    int x1 = min(4, max(0, (int)x0f + 1));

    const float* g = g_grid + (size_t)b * 75;
    float* o = out + (size_t)idx * 3;
    #pragma unroll
    for (int c = 0; c < 3; c++) {
        float v00 = __ldg(&g[(y0 * 5 + x0) * 3 + c]);
        float v01 = __ldg(&g[(y0 * 5 + x1) * 3 + c]);
        float v10 = __ldg(&g[(y1 * 5 + x0) * 3 + c]);
        float v11 = __ldg(&g[(y1 * 5 + x1) * 3 + c]);
        float top = v00 * (1.0f - wx) + v01 * wx;
        float bot = v10 * (1.0f - wx) + v11 * wx;
        o[c] = top * (1.0f - wy) + bot * wy;
    }
}

// ---------------------------------------------------------------------------
extern "C" void kernel_launch(void* const* d_in, const int* in_sizes, int n_in,
                              void* d_out, int out_size) {
    const float* in = (const float*)d_in[0];
    float* out = (float*)d_out;
    const int npix = BATCH * IMG_PIX;

    transpose_kernel<<<(npix + 255) / 256, 256>>>(in);
    compute_kernel<<<5 * BATCH * 3, 256>>>();
    resize_kernel<<<(npix + 255) / 256, 256>>>(out);
}

// round 6
// speedup vs baseline: 1.7229x; 1.6903x over previous
#include <cuda_runtime.h>
#include <math.h>

#define BATCH 64
#define HW 224
#define IMG_PIX (HW * HW)   // 50176
#define NPIX (BATCH * IMG_PIX)

// Scratch: channel-planar copy of the input + the 5x5x3 metric grid per image.
__device__ float g_planar[3ULL * NPIX];      // [ch][b][r][c]
__device__ float g_grid[BATCH * 5 * 5 * 3];  // [b][metric][kidx][ch]

// ---------------------------------------------------------------------------
// Pass 1: NHWC -> planar, float4-vectorized (4 pixels / thread)
// ---------------------------------------------------------------------------
__global__ void transpose_kernel(const float* __restrict__ in) {
    int g = blockIdx.x * blockDim.x + threadIdx.x;   // group of 4 pixels
    if (g >= NPIX / 4) return;
    const float4* p = (const float4*)(in + (size_t)g * 12);
    float4 A = __ldg(&p[0]);   // p0.r p0.g p0.b p1.r
    float4 B = __ldg(&p[1]);   // p1.g p1.b p2.r p2.g
    float4 C = __ldg(&p[2]);   // p2.b p3.r p3.g p3.b
    float4 rch = make_float4(A.x, A.w, B.z, C.y);
    float4 gch = make_float4(A.y, B.x, B.w, C.z);
    float4 bch = make_float4(A.z, B.y, C.x, C.w);
    ((float4*)(g_planar + 0ULL * NPIX))[g] = rch;
    ((float4*)(g_planar + 1ULL * NPIX))[g] = gch;
    ((float4*)(g_planar + 2ULL * NPIX))[g] = bch;
}

// ---------------------------------------------------------------------------
// Pass 2: per-(b, ch, k) block computes all patches and the 5 metrics
// ---------------------------------------------------------------------------
template <int K>
__device__ __forceinline__ void compute_block(int b, int ch, int kidx) {
    constexpr int ROWS = (HW + K - 1) / K;
    constexpr int P = ROWS * ROWS;
    constexpr int PAD = (ROWS * K - HW) / 2;   // top/left pad (== ph // 2)
    constexpr int KK = K * K;
    constexpr unsigned MASK = (1u << K) - 1u;

    __shared__ int s_hist[KK + 1];
    __shared__ int s_ncomp, s_perc, s_marea;

    for (int i = threadIdx.x; i < KK + 1; i += blockDim.x) s_hist[i] = 0;
    if (threadIdx.x == 0) { s_ncomp = 0; s_perc = 0; s_marea = 0; }
    __syncthreads();

    const float* img = g_planar + ((size_t)ch * BATCH + b) * IMG_PIX;
    const float thr = (float)K;

    int t_ncomp = 0, t_perc = 0, t_marea = 0;

    for (int p = threadIdx.x; p < P; p += blockDim.x) {
        int pr = p / ROWS, pc = p - pr * ROWS;
        int r0 = pr * K - PAD, c0 = pc * K - PAD;

        // center pixel is always in-bounds for these (K, 224) combos
        float cv = __ldg(&img[(r0 + K / 2) * HW + (c0 + K / 2)]);

        // ---- binarize patch into K row bitmasks ----
        unsigned rows[K];
        int ones = 0;
        bool colfast = (c0 >= 0) && (c0 + K <= HW);
        #pragma unroll
        for (int rr = 0; rr < K; rr++) {
            int r = r0 + rr;
            unsigned m = 0;
            if (r >= 0 && r < HW) {
                if (colfast) {
                    const float* rp = img + r * HW + c0;
                    #pragma unroll
                    for (int cc = 0; cc < K; cc++) {
                        float v = __ldg(&rp[cc]);
                        m |= (fabsf(v - cv) <= thr) ? (1u << cc) : 0u;
                    }
                } else {
                    #pragma unroll
                    for (int cc = 0; cc < K; cc++) {
                        int c = c0 + cc;
                        float v = (c >= 0 && c < HW) ? __ldg(&img[r * HW + c]) : 0.0f;
                        m |= (fabsf(v - cv) <= thr) ? (1u << cc) : 0u;
                    }
                }
            } else {
                m = (cv <= thr) ? MASK : 0u;   // fully-padded row (values 0)
            }
            rows[rr] = m;
            ones += __popc(m);
        }

        // ---- bulk strip of singletons and isolated dominoes (branch-free) ----
        // Bit-sliced 4-neighbor count: iso = 0 neighbors, e1 = exactly 1.
        unsigned rem[K];
        int n_iso = 0, n_dom = 0;
        unsigned e1p = 0;
        #pragma unroll
        for (int i = 0; i < K; i++) {
            unsigned l = (rows[i] << 1) & MASK;
            unsigned r = rows[i] >> 1;
            unsigned u = (i > 0) ? rows[i - 1] : 0u;
            unsigned d = (i < K - 1) ? rows[i + 1] : 0u;
            unsigned s  = l ^ r, ca = l & r;
            unsigned t2 = u ^ d, cb = u & d;
            unsigned low = s ^ t2;
            unsigned ge2 = ca | cb | (s & t2);
            unsigned any = low | ge2;
            unsigned e1  = rows[i] & low & ~ge2;

            n_iso += __popc(rows[i] & ~any);
            unsigned rm = rows[i] & any;

            unsigned hd = e1 & (e1 >> 1);        // isolated horizontal dominoes
            n_dom += __popc(hd);
            rm &= ~(hd | ((hd << 1) & MASK));

            unsigned vd = e1p & e1;              // isolated vertical dominoes
            n_dom += __popc(vd);
            rm &= ~vd;
            if (i > 0) rem[i - 1] &= ~vd;

            rem[i] = rm;
            e1p = e1;
        }

        int remaining = ones - n_iso - 2 * n_dom;
        int ncomp = n_iso + n_dom;
        int maxc = (n_dom > 0) ? 2 : ((n_iso > 0) ? 1 : 0);

        // ---- flood-fill only the residual clustered cells ----
        while (remaining > 0) {
            unsigned comp[K];
            #pragma unroll
            for (int i = 0; i < K; i++) comp[i] = 0;
            int seeded = 0;
            #pragma unroll
            for (int i = 0; i < K; i++) {
                if (!seeded && rem[i]) { comp[i] = rem[i] & (0u - rem[i]); seeded = 1; }
            }
            int changed = 1;
            while (changed) {
                changed = 0;
                #pragma unroll
                for (int i = 0; i < K; i++) {          // downward sweep
                    unsigned acc = comp[i] | (comp[i] << 1) | (comp[i] >> 1);
                    if (i > 0) acc |= comp[i - 1];
                    if (i < K - 1) acc |= comp[i + 1];
                    acc &= rem[i];
                    if (acc != comp[i]) { comp[i] = acc; changed = 1; }
                }
                #pragma unroll
                for (int i = K - 1; i >= 0; i--) {     // upward sweep
                    unsigned acc = comp[i] | (comp[i] << 1) | (comp[i] >> 1);
                    if (i > 0) acc |= comp[i - 1];
                    if (i < K - 1) acc |= comp[i + 1];
                    acc &= rem[i];
                    if (acc != comp[i]) { comp[i] = acc; changed = 1; }
                }
            }
            int sz = 0;
            #pragma unroll
            for (int i = 0; i < K; i++) { sz += __popc(comp[i]); rem[i] &= ~comp[i]; }
            remaining -= sz;
            ncomp++;
            if (sz > maxc) maxc = sz;
        }

        int zeros = KK - ones;
        int marea = (zeros > maxc) ? zeros : maxc;   // label-0 (bg) count vs max comp
        int perc = ((float)ones / (float)KK >= 0.59275f) ? 1 : 0;

        atomicAdd(&s_hist[ones], 1);
        t_ncomp += ncomp;
        t_perc += perc;
        t_marea += marea;
    }

    // warp-reduce the three scalar sums, then one shared atomic per warp
    #pragma unroll
    for (int off = 16; off > 0; off >>= 1) {
        t_ncomp += __shfl_down_sync(0xffffffffu, t_ncomp, off);
        t_perc  += __shfl_down_sync(0xffffffffu, t_perc, off);
        t_marea += __shfl_down_sync(0xffffffffu, t_marea, off);
    }
    if ((threadIdx.x & 31) == 0) {
        atomicAdd(&s_ncomp, t_ncomp);
        atomicAdd(&s_perc, t_perc);
        atomicAdd(&s_marea, t_marea);
    }
    __syncthreads();

    if (threadIdx.x == 0) {
        const float Pf = (float)P;
        float fd = 0.f, m = 0.f, m2 = 0.f;
        for (int j = 0; j < KK; j++) {            // bin KK intentionally dropped
            float pr = (float)s_hist[j] / Pf;
            float n = (float)(j + 1);
            fd += pr / n;
            m  += pr * n;
            m2 += pr * pr * n;
        }
        float lac = (m2 - m * m) / (m * m);
        float acn  = (float)(s_ncomp / P);        // tf integer reduce_mean
        float acp  = (float)(s_perc  / P);
        float acma = (float)(s_marea / P);

        float* g = g_grid + (size_t)b * 75;       // [metric][kidx][ch]
        g[(0 * 5 + kidx) * 3 + ch] = acn;
        g[(1 * 5 + kidx) * 3 + ch] = acp;
        g[(2 * 5 + kidx) * 3 + ch] = acma;
        g[(3 * 5 + kidx) * 3 + ch] = lac;
        g[(4 * 5 + kidx) * 3 + ch] = fd;
    }
}

__global__ __launch_bounds__(256) void compute_kernel() {
    int bid = blockIdx.x;
    int kidx = bid / (BATCH * 3);
    int rest = bid - kidx * (BATCH * 3);
    int b = rest / 3, ch = rest - (rest / 3) * 3;
    switch (kidx) {
        case 0: compute_block<3>(b, ch, 0); break;
        case 1: compute_block<5>(b, ch, 1); break;
        case 2: compute_block<7>(b, ch, 2); break;
        case 3: compute_block<9>(b, ch, 3); break;
        case 4: compute_block<11>(b, ch, 4); break;
    }
}

// ---------------------------------------------------------------------------
// Pass 3: bilinear upsample 5x5x3 -> 224x224x3, float4-vectorized stores
// (half-pixel centers + edge clamp == jax.image.resize 'bilinear' upsampling)
// ---------------------------------------------------------------------------
__global__ void resize_kernel(float* __restrict__ out) {
    int g = blockIdx.x * blockDim.x + threadIdx.x;   // group of 4 pixels
    if (g >= NPIX / 4) return;
    int b = g / (IMG_PIX / 4);
    int within = g - b * (IMG_PIX / 4);
    int pix0 = within * 4;
    int i = pix0 / HW, j0 = pix0 - (pix0 / HW) * HW;  // 4 pixels share row i

    const float scale = 5.0f / 224.0f;
    float fy = ((float)i + 0.5f) * scale - 0.5f;
    float y0f = floorf(fy);
    float wy = fy - y0f;
    int y0 = min(4, max(0, (int)y0f));
    int y1 = min(4, max(0, (int)y0f + 1));

    const float* gr = g_grid + (size_t)b * 75;
    float vals[12];
    #pragma unroll
    for (int q = 0; q < 4; q++) {
        int j = j0 + q;
        float fx = ((float)j + 0.5f) * scale - 0.5f;
        float x0f = floorf(fx);
        float wx = fx - x0f;
        int x0 = min(4, max(0, (int)x0f));
        int x1 = min(4, max(0, (int)x0f + 1));
        #pragma unroll
        for (int c = 0; c < 3; c++) {
            float v00 = __ldg(&gr[(y0 * 5 + x0) * 3 + c]);
            float v01 = __ldg(&gr[(y0 * 5 + x1) * 3 + c]);
            float v10 = __ldg(&gr[(y1 * 5 + x0) * 3 + c]);
            float v11 = __ldg(&gr[(y1 * 5 + x1) * 3 + c]);
            float top = v00 * (1.0f - wx) + v01 * wx;
            float bot = v10 * (1.0f - wx) + v11 * wx;
            vals[q * 3 + c] = top * (1.0f - wy) + bot * wy;
        }
    }
    float4* o = (float4*)(out + (size_t)(b * IMG_PIX + pix0) * 3);
    o[0] = make_float4(vals[0], vals[1], vals[2],  vals[3]);
    o[1] = make_float4(vals[4], vals[5], vals[6],  vals[7]);
    o[2] = make_float4(vals[8], vals[9], vals[10], vals[11]);
}

// ---------------------------------------------------------------------------
extern "C" void kernel_launch(void* const* d_in, const int* in_sizes, int n_in,
                              void* d_out, int out_size) {
    const float* in = (const float*)d_in[0];
    float* out = (float*)d_out;

    transpose_kernel<<<(NPIX / 4 + 255) / 256, 256>>>(in);
    compute_kernel<<<5 * BATCH * 3, 256>>>();
    resize_kernel<<<(NPIX / 4 + 255) / 256, 256>>>(out);
}